// round 3
// baseline (speedup 1.0000x reference)
#include <cuda_runtime.h>
#include <math.h>

// out[row] = tanh(sqrt(sum_j (w[row][j] - x[j])^2)), row in [0, 1048576), j in [0, 256)
// Warp handles FOUR rows: 8 independent front-batched 128-bit streaming loads
// (each 512B fully-coalesced) -> maximal DRAM MLP per warp.

__global__ __launch_bounds__(256) void sonia_l2_tanh_kernel4(
    const float* __restrict__ x,
    const float* __restrict__ w,
    float* __restrict__ out,
    int n_rows)
{
    const int warp_id = (blockIdx.x * blockDim.x + threadIdx.x) >> 5;
    const int lane    = threadIdx.x & 31;
    const int row0    = warp_id * 4;
    if (row0 >= n_rows) return;

    const float4* __restrict__ wr = reinterpret_cast<const float4*>(w) + (size_t)row0 * 64;
    const float4* __restrict__ xr = reinterpret_cast<const float4*>(x);

    // x is tiny and re-read by every warp: L1/L2 resident.
    const float4 x0 = __ldg(xr + lane);
    const float4 x1 = __ldg(xr + lane + 32);

    // 8 independent streaming loads (evict-first: pure pass-through data).
    const float4 a0 = __ldcs(wr + lane);
    const float4 a1 = __ldcs(wr + lane + 32);
    const float4 b0 = __ldcs(wr + lane + 64);
    const float4 b1 = __ldcs(wr + lane + 96);
    const float4 c0 = __ldcs(wr + lane + 128);
    const float4 c1 = __ldcs(wr + lane + 160);
    const float4 e0 = __ldcs(wr + lane + 192);
    const float4 e1 = __ldcs(wr + lane + 224);

    float d;
    float sa = 0.0f, sb = 0.0f, sc = 0.0f, se = 0.0f;

    d = a0.x - x0.x; sa = fmaf(d, d, sa);
    d = a0.y - x0.y; sa = fmaf(d, d, sa);
    d = a0.z - x0.z; sa = fmaf(d, d, sa);
    d = a0.w - x0.w; sa = fmaf(d, d, sa);
    d = a1.x - x1.x; sa = fmaf(d, d, sa);
    d = a1.y - x1.y; sa = fmaf(d, d, sa);
    d = a1.z - x1.z; sa = fmaf(d, d, sa);
    d = a1.w - x1.w; sa = fmaf(d, d, sa);

    d = b0.x - x0.x; sb = fmaf(d, d, sb);
    d = b0.y - x0.y; sb = fmaf(d, d, sb);
    d = b0.z - x0.z; sb = fmaf(d, d, sb);
    d = b0.w - x0.w; sb = fmaf(d, d, sb);
    d = b1.x - x1.x; sb = fmaf(d, d, sb);
    d = b1.y - x1.y; sb = fmaf(d, d, sb);
    d = b1.z - x1.z; sb = fmaf(d, d, sb);
    d = b1.w - x1.w; sb = fmaf(d, d, sb);

    d = c0.x - x0.x; sc = fmaf(d, d, sc);
    d = c0.y - x0.y; sc = fmaf(d, d, sc);
    d = c0.z - x0.z; sc = fmaf(d, d, sc);
    d = c0.w - x0.w; sc = fmaf(d, d, sc);
    d = c1.x - x1.x; sc = fmaf(d, d, sc);
    d = c1.y - x1.y; sc = fmaf(d, d, sc);
    d = c1.z - x1.z; sc = fmaf(d, d, sc);
    d = c1.w - x1.w; sc = fmaf(d, d, sc);

    d = e0.x - x0.x; se = fmaf(d, d, se);
    d = e0.y - x0.y; se = fmaf(d, d, se);
    d = e0.z - x0.z; se = fmaf(d, d, se);
    d = e0.w - x0.w; se = fmaf(d, d, se);
    d = e1.x - x1.x; se = fmaf(d, d, se);
    d = e1.y - x1.y; se = fmaf(d, d, se);
    d = e1.z - x1.z; se = fmaf(d, d, se);
    d = e1.w - x1.w; se = fmaf(d, d, se);

    // Butterfly reduce all four sums across the warp.
    #pragma unroll
    for (int off = 16; off > 0; off >>= 1) {
        sa += __shfl_xor_sync(0xFFFFFFFFu, sa, off);
        sb += __shfl_xor_sync(0xFFFFFFFFu, sb, off);
        sc += __shfl_xor_sync(0xFFFFFFFFu, sc, off);
        se += __shfl_xor_sync(0xFFFFFFFFu, se, off);
    }

    if (lane == 0) {
        // n_rows is a multiple of 4 here (1048576), but guard anyway.
        out[row0] = tanhf(sqrtf(sa));
        if (row0 + 1 < n_rows) out[row0 + 1] = tanhf(sqrtf(sb));
        if (row0 + 2 < n_rows) out[row0 + 2] = tanhf(sqrtf(sc));
        if (row0 + 3 < n_rows) out[row0 + 3] = tanhf(sqrtf(se));
    }
}

extern "C" void kernel_launch(void* const* d_in, const int* in_sizes, int n_in,
                              void* d_out, int out_size)
{
    const float* x = (const float*)d_in[0];   // input  [1, 256]
    const float* w = (const float*)d_in[1];   // weight [out_size, 256]
    float* out     = (float*)d_out;

    const int n_rows = out_size;              // 1048576
    // 8 warps/block, 4 rows/warp -> 32 rows per block
    const int rows_per_block = 32;
    const int blocks = (n_rows + rows_per_block - 1) / rows_per_block;

    sonia_l2_tanh_kernel4<<<blocks, 256>>>(x, w, out, n_rows);
}

// round 4
// speedup vs baseline: 1.0027x; 1.0027x over previous
#include <cuda_runtime.h>
#include <math.h>

// out[row] = tanh(sqrt(sum_j (w[row][j] - x[j])^2)), row in [0, 1048576), j in [0, 256)
// Warp handles FOUR rows: 8 independent front-batched 128-bit streaming loads.
// __launch_bounds__(256, 4) raises the reg budget to 64/thread so ptxas can
// actually keep all 8 loads in flight (at the default 32-reg target it staged
// them and MLP collapsed -- R3 regression).

__global__ __launch_bounds__(256, 4) void sonia_l2_tanh_kernel4b(
    const float* __restrict__ x,
    const float* __restrict__ w,
    float* __restrict__ out,
    int n_rows)
{
    const int warp_id = (blockIdx.x * blockDim.x + threadIdx.x) >> 5;
    const int lane    = threadIdx.x & 31;
    const int row0    = warp_id * 4;
    if (row0 >= n_rows) return;

    const float4* __restrict__ wr = reinterpret_cast<const float4*>(w) + (size_t)row0 * 64;
    const float4* __restrict__ xr = reinterpret_cast<const float4*>(x);

    // x is tiny and re-read by every warp: L1/L2 resident.
    const float4 x0 = __ldg(xr + lane);
    const float4 x1 = __ldg(xr + lane + 32);

    // 8 independent streaming loads (evict-first: pure pass-through data).
    const float4 a0 = __ldcs(wr + lane);
    const float4 a1 = __ldcs(wr + lane + 32);
    const float4 b0 = __ldcs(wr + lane + 64);
    const float4 b1 = __ldcs(wr + lane + 96);
    const float4 c0 = __ldcs(wr + lane + 128);
    const float4 c1 = __ldcs(wr + lane + 160);
    const float4 e0 = __ldcs(wr + lane + 192);
    const float4 e1 = __ldcs(wr + lane + 224);

    float d;
    float sa = 0.0f, sb = 0.0f, sc = 0.0f, se = 0.0f;

    d = a0.x - x0.x; sa = fmaf(d, d, sa);
    d = a0.y - x0.y; sa = fmaf(d, d, sa);
    d = a0.z - x0.z; sa = fmaf(d, d, sa);
    d = a0.w - x0.w; sa = fmaf(d, d, sa);
    d = a1.x - x1.x; sa = fmaf(d, d, sa);
    d = a1.y - x1.y; sa = fmaf(d, d, sa);
    d = a1.z - x1.z; sa = fmaf(d, d, sa);
    d = a1.w - x1.w; sa = fmaf(d, d, sa);

    d = b0.x - x0.x; sb = fmaf(d, d, sb);
    d = b0.y - x0.y; sb = fmaf(d, d, sb);
    d = b0.z - x0.z; sb = fmaf(d, d, sb);
    d = b0.w - x0.w; sb = fmaf(d, d, sb);
    d = b1.x - x1.x; sb = fmaf(d, d, sb);
    d = b1.y - x1.y; sb = fmaf(d, d, sb);
    d = b1.z - x1.z; sb = fmaf(d, d, sb);
    d = b1.w - x1.w; sb = fmaf(d, d, sb);

    d = c0.x - x0.x; sc = fmaf(d, d, sc);
    d = c0.y - x0.y; sc = fmaf(d, d, sc);
    d = c0.z - x0.z; sc = fmaf(d, d, sc);
    d = c0.w - x0.w; sc = fmaf(d, d, sc);
    d = c1.x - x1.x; sc = fmaf(d, d, sc);
    d = c1.y - x1.y; sc = fmaf(d, d, sc);
    d = c1.z - x1.z; sc = fmaf(d, d, sc);
    d = c1.w - x1.w; sc = fmaf(d, d, sc);

    d = e0.x - x0.x; se = fmaf(d, d, se);
    d = e0.y - x0.y; se = fmaf(d, d, se);
    d = e0.z - x0.z; se = fmaf(d, d, se);
    d = e0.w - x0.w; se = fmaf(d, d, se);
    d = e1.x - x1.x; se = fmaf(d, d, se);
    d = e1.y - x1.y; se = fmaf(d, d, se);
    d = e1.z - x1.z; se = fmaf(d, d, se);
    d = e1.w - x1.w; se = fmaf(d, d, se);

    // Butterfly reduce all four sums across the warp.
    #pragma unroll
    for (int off = 16; off > 0; off >>= 1) {
        sa += __shfl_xor_sync(0xFFFFFFFFu, sa, off);
        sb += __shfl_xor_sync(0xFFFFFFFFu, sb, off);
        sc += __shfl_xor_sync(0xFFFFFFFFu, sc, off);
        se += __shfl_xor_sync(0xFFFFFFFFu, se, off);
    }

    if (lane == 0) {
        out[row0] = tanhf(sqrtf(sa));
        if (row0 + 1 < n_rows) out[row0 + 1] = tanhf(sqrtf(sb));
        if (row0 + 2 < n_rows) out[row0 + 2] = tanhf(sqrtf(sc));
        if (row0 + 3 < n_rows) out[row0 + 3] = tanhf(sqrtf(se));
    }
}

extern "C" void kernel_launch(void* const* d_in, const int* in_sizes, int n_in,
                              void* d_out, int out_size)
{
    const float* x = (const float*)d_in[0];   // input  [1, 256]
    const float* w = (const float*)d_in[1];   // weight [out_size, 256]
    float* out     = (float*)d_out;

    const int n_rows = out_size;              // 1048576
    // 8 warps/block, 4 rows/warp -> 32 rows per block
    const int rows_per_block = 32;
    const int blocks = (n_rows + rows_per_block - 1) / rows_per_block;

    sonia_l2_tanh_kernel4b<<<blocks, 256>>>(x, w, out, n_rows);
}